// round 1
// baseline (speedup 1.0000x reference)
#include <cuda_runtime.h>
#include <cuda_bf16.h>
#include <math.h>

// Problem constants
#define B_SZ   2
#define LSEQ   1024
#define DM     768
#define NST    16
#define KCONV  4
#define DRANK  48
#define XPW    (DRANK + 2*NST)   // 80
#define W2     (2*DM)            // 1536
#define MROWS  (B_SZ*LSEQ)       // 2048

// ---------------- device scratch (no allocations allowed) ----------------
__device__ float g_xr[(size_t)MROWS * W2];        // (2048,1536) : [xs_raw | res]
__device__ float g_xs[(size_t)MROWS * DM];        // post conv+silu
__device__ float g_xp[(size_t)MROWS * XPW];       // [delta_r(48) | B(16) | C(16)]
__device__ float g_delta[(size_t)MROWS * DM];     // softplus+clip
__device__ float g_E[(size_t)B_SZ * DM * LSEQ * NST];   // exp(cs) per (b,d,t,n) ~100MB
__device__ float g_yg[(size_t)MROWS * DM];        // gated scan output

// ---------------- generic tiled SGEMM: C = A(MxK)*B(KxN) ----------------
// EPI=0: plain store. EPI=1: +bias, softplus, clip[1e-4,0.1].
template<int EPI>
__global__ void sgemm_k(const float* __restrict__ A, const float* __restrict__ B,
                        const float* __restrict__ bias, float* __restrict__ C,
                        int M, int N, int K, int lda, int ldb, int ldc)
{
    const int BM = 64, BN = 64, BK = 16;
    __shared__ float As[64][16];
    __shared__ float Bs[16][65];

    int tid = threadIdx.x;
    int tx = tid & 15;        // col group
    int ty = tid >> 4;        // row group
    int rowBase = blockIdx.y * BM;
    int colBase = blockIdx.x * BN;

    float acc[4][4] = {};

    for (int kt = 0; kt < K; kt += BK) {
        #pragma unroll
        for (int i = 0; i < 4; i++) {
            int idx = tid + i * 256;
            int m = idx >> 4, k = idx & 15;
            int gm = rowBase + m, gk = kt + k;
            As[m][k] = (gm < M && gk < K) ? A[(size_t)gm * lda + gk] : 0.f;
        }
        #pragma unroll
        for (int i = 0; i < 4; i++) {
            int idx = tid + i * 256;
            int k = idx >> 6, n = idx & 63;
            int gk = kt + k, gn = colBase + n;
            Bs[k][n] = (gk < K && gn < N) ? B[(size_t)gk * ldb + gn] : 0.f;
        }
        __syncthreads();

        #pragma unroll
        for (int kk = 0; kk < BK; kk++) {
            float a[4], b[4];
            #pragma unroll
            for (int i = 0; i < 4; i++) a[i] = As[ty * 4 + i][kk];
            #pragma unroll
            for (int j = 0; j < 4; j++) b[j] = Bs[kk][tx * 4 + j];
            #pragma unroll
            for (int i = 0; i < 4; i++)
                #pragma unroll
                for (int j = 0; j < 4; j++)
                    acc[i][j] += a[i] * b[j];
        }
        __syncthreads();
    }

    #pragma unroll
    for (int i = 0; i < 4; i++) {
        int gm = rowBase + ty * 4 + i;
        if (gm >= M) continue;
        #pragma unroll
        for (int j = 0; j < 4; j++) {
            int gn = colBase + tx * 4 + j;
            if (gn >= N) continue;
            float v = acc[i][j];
            if (EPI == 1) {
                v += bias[gn];
                // stable softplus: max(z,0)+log1p(exp(-|z|))
                v = fmaxf(v, 0.f) + log1pf(expf(-fabsf(v)));
                v = fminf(fmaxf(v, 1e-4f), 0.1f);
            }
            C[(size_t)gm * ldc + gn] = v;
        }
    }
}

// ---------------- depthwise causal conv (K=4) + SiLU ----------------
__global__ void conv_silu_k(const float* __restrict__ xr,
                            const float* __restrict__ cw,
                            const float* __restrict__ cb,
                            float* __restrict__ xs)
{
    int idx = blockIdx.x * blockDim.x + threadIdx.x;
    if (idx >= MROWS * DM) return;
    int d = idx % DM;
    int t = (idx / DM) % LSEQ;
    int b = idx / (DM * LSEQ);

    float acc = cb[d];
    #pragma unroll
    for (int k = 0; k < KCONV; k++) {
        int tt = t - (KCONV - 1) + k;
        if (tt >= 0)
            acc += xr[((size_t)(b * LSEQ + tt)) * W2 + d] * cw[d * KCONV + k];
    }
    xs[idx] = acc / (1.f + expf(-acc));   // silu
}

// ---------------- scan backward pass: store exp(cs_t) ----------------
// cs_{L-1}=0 ; cs_{t-1} = cs_t + dA_t  (dA_t = delta_t * A_n), summed from the end
// exactly like jnp.flip+cumsum+flip in the reference.
__global__ void scan_bwd_k(const float* __restrict__ delta,
                           const float* __restrict__ A_log,
                           float* __restrict__ E)
{
    int w = (blockIdx.x * blockDim.x + threadIdx.x) >> 5;
    int lane = threadIdx.x & 31;
    if (w >= B_SZ * DM) return;
    int b = w / DM, d = w % DM;
    int n = lane & 15;

    float An = -expf(A_log[d * NST + n]);
    float s = 0.f;
    const float* dptr = delta + (size_t)b * LSEQ * DM + d;
    float* eptr = E + ((size_t)(b * DM + d) * LSEQ) * NST + n;

    for (int t = LSEQ - 1; t >= 0; t--) {
        float dlt = dptr[(size_t)t * DM];
        if (lane < 16) eptr[(size_t)t * NST] = expf(s);
        s += dlt * An;
    }
}

// ---------------- scan forward pass + C-projection + D skip + gate ----------------
__global__ void scan_fwd_k(const float* __restrict__ delta,
                           const float* __restrict__ xs,
                           const float* __restrict__ xp,
                           const float* __restrict__ E,
                           const float* __restrict__ Dp,
                           const float* __restrict__ xr,
                           float* __restrict__ yg)
{
    int w = (blockIdx.x * blockDim.x + threadIdx.x) >> 5;
    int lane = threadIdx.x & 31;
    if (w >= B_SZ * DM) return;
    int b = w / DM, d = w % DM;
    int n = lane & 15;

    float Dd = Dp[d];
    float num = 0.f;
    const float* eptr = E + ((size_t)(b * DM + d) * LSEQ) * NST + n;

    for (int t = 0; t < LSEQ; t++) {
        size_t bt = (size_t)(b * LSEQ + t);
        float e   = eptr[(size_t)t * NST];
        float dlt = delta[bt * DM + d];
        float u   = xs[bt * DM + d];
        float Bn  = xp[bt * XPW + DRANK + n];
        float Cn  = xp[bt * XPW + DRANK + NST + n];

        num += dlt * u * Bn * e;                 // cumsum(dB_u * dA_cs)
        float yn = (num / (e + 1e-12f)) * Cn;    // xs_state * C

        // sum over 16 states (lanes 0..15; upper half mirrors, harmless)
        yn += __shfl_xor_sync(0xffffffffu, yn, 1);
        yn += __shfl_xor_sync(0xffffffffu, yn, 2);
        yn += __shfl_xor_sync(0xffffffffu, yn, 4);
        yn += __shfl_xor_sync(0xffffffffu, yn, 8);

        if (lane == 0) {
            float y = yn + u * Dd;
            float r = xr[bt * W2 + DM + d];          // res
            yg[bt * DM + d] = y * (r / (1.f + expf(-r)));  // * silu(res)
        }
    }
}

// ---------------- launch ----------------
extern "C" void kernel_launch(void* const* d_in, const int* in_sizes, int n_in,
                              void* d_out, int out_size)
{
    const float* x       = (const float*)d_in[0];
    const float* W_in    = (const float*)d_in[1];
    const float* conv_w  = (const float*)d_in[2];
    const float* conv_b  = (const float*)d_in[3];
    const float* W_x     = (const float*)d_in[4];
    const float* W_delta = (const float*)d_in[5];
    const float* b_delta = (const float*)d_in[6];
    const float* A_log   = (const float*)d_in[7];
    const float* D_param = (const float*)d_in[8];
    const float* W_out   = (const float*)d_in[9];
    float* out = (float*)d_out;

    float *p_xr, *p_xs, *p_xp, *p_delta, *p_E, *p_yg;
    cudaGetSymbolAddress((void**)&p_xr,    g_xr);
    cudaGetSymbolAddress((void**)&p_xs,    g_xs);
    cudaGetSymbolAddress((void**)&p_xp,    g_xp);
    cudaGetSymbolAddress((void**)&p_delta, g_delta);
    cudaGetSymbolAddress((void**)&p_E,     g_E);
    cudaGetSymbolAddress((void**)&p_yg,    g_yg);

    // 1) xr = x @ W_in   (2048 x 1536, K=768)
    sgemm_k<0><<<dim3((W2 + 63) / 64, (MROWS + 63) / 64), 256>>>(
        x, W_in, nullptr, p_xr, MROWS, W2, DM, DM, W2, W2);

    // 2) depthwise causal conv + silu -> xs
    conv_silu_k<<<(MROWS * DM + 255) / 256, 256>>>(p_xr, conv_w, conv_b, p_xs);

    // 3) xp = xs @ W_x   (2048 x 80, K=768)
    sgemm_k<0><<<dim3((XPW + 63) / 64, (MROWS + 63) / 64), 256>>>(
        p_xs, W_x, nullptr, p_xp, MROWS, XPW, DM, DM, XPW, XPW);

    // 4) delta = clip(softplus(xp[:, :48] @ W_delta + b_delta))   (2048 x 768, K=48)
    sgemm_k<1><<<dim3((DM + 63) / 64, (MROWS + 63) / 64), 256>>>(
        p_xp, W_delta, b_delta, p_delta, MROWS, DM, DRANK, XPW, DM, DM);

    // 5) selective scan: backward exp(cs) pass, then forward cumsum + gate
    int scan_threads = B_SZ * DM * 32;          // one warp per (b,d)
    scan_bwd_k<<<(scan_threads + 255) / 256, 256>>>(p_delta, A_log, p_E);
    scan_fwd_k<<<(scan_threads + 255) / 256, 256>>>(p_delta, p_xs, p_xp, p_E,
                                                    D_param, p_xr, p_yg);

    // 6) out = yg @ W_out   (2048 x 768, K=768)
    sgemm_k<0><<<dim3((DM + 63) / 64, (MROWS + 63) / 64), 256>>>(
        p_yg, W_out, nullptr, out, MROWS, DM, DM, DM, DM, DM);
}

// round 2
// speedup vs baseline: 3.9190x; 3.9190x over previous
#include <cuda_runtime.h>
#include <cuda_bf16.h>
#include <math.h>

#define B_SZ   2
#define LSEQ   1024
#define DM     768
#define NST    16
#define KCONV  4
#define DRANK  48
#define XPW    (DRANK + 2*NST)   // 80
#define W2     (2*DM)            // 1536
#define MROWS  (B_SZ*LSEQ)       // 2048

// ---------------- device scratch ----------------
__device__ float g_xr[(size_t)MROWS * W2];        // [bt][1536] : [xs_raw | res]
__device__ float g_xs[(size_t)MROWS * DM];        // conv+silu, [bt][d]
__device__ float g_xsT[(size_t)B_SZ * DM * LSEQ]; // [bd][t]
__device__ float g_gateT[(size_t)B_SZ * DM * LSEQ]; // silu(res), [bd][t]
__device__ float g_xp[(size_t)MROWS * XPW];       // [delta_r(48)|B(16)|C(16)]
__device__ float g_delta[(size_t)MROWS * DM];     // [bt][d]
__device__ float g_deltaT[(size_t)B_SZ * DM * LSEQ]; // [bd][t]
__device__ float g_yg[(size_t)MROWS * DM];        // gated scan out [bt][d]

// ================= 128x128x8 SGEMM, 8x8 per thread =================
// Requires M%128==0, N%128==0, K%8==0, lda/ldb/ldc %4==0 (all call sites satisfy).
// EPI=0: plain. EPI=1: +bias, softplus, clip, and scatter-store transposed copy.
template<int EPI>
__global__ __launch_bounds__(256) void sgemm128_k(
    const float* __restrict__ A, const float* __restrict__ B,
    const float* __restrict__ bias, float* __restrict__ C,
    float* __restrict__ CT,
    int M, int N, int K, int lda, int ldb, int ldc)
{
    __shared__ float As[8][128];
    __shared__ float Bs[8][128];

    int tid = threadIdx.x;
    int tx = tid & 15, ty = tid >> 4;
    int mBase = blockIdx.y * 128, nBase = blockIdx.x * 128;

    int arow = tid >> 1;            // 0..127
    int acol = (tid & 1) * 4;       // 0 or 4
    int brow = tid >> 5;            // 0..7
    int bcol = (tid & 31) * 4;

    float acc[8][8] = {};

    for (int k0 = 0; k0 < K; k0 += 8) {
        float4 av = *(const float4*)&A[(size_t)(mBase + arow) * lda + k0 + acol];
        float4 bv = *(const float4*)&B[(size_t)(k0 + brow) * ldb + nBase + bcol];
        __syncthreads();
        As[acol + 0][arow] = av.x;
        As[acol + 1][arow] = av.y;
        As[acol + 2][arow] = av.z;
        As[acol + 3][arow] = av.w;
        *(float4*)&Bs[brow][bcol] = bv;
        __syncthreads();

        #pragma unroll
        for (int kk = 0; kk < 8; kk++) {
            float ar[8], br[8];
            float4 a0 = *(const float4*)&As[kk][ty * 4];
            float4 a1 = *(const float4*)&As[kk][64 + ty * 4];
            float4 b0 = *(const float4*)&Bs[kk][tx * 4];
            float4 b1 = *(const float4*)&Bs[kk][64 + tx * 4];
            ar[0]=a0.x; ar[1]=a0.y; ar[2]=a0.z; ar[3]=a0.w;
            ar[4]=a1.x; ar[5]=a1.y; ar[6]=a1.z; ar[7]=a1.w;
            br[0]=b0.x; br[1]=b0.y; br[2]=b0.z; br[3]=b0.w;
            br[4]=b1.x; br[5]=b1.y; br[6]=b1.z; br[7]=b1.w;
            #pragma unroll
            for (int i = 0; i < 8; i++)
                #pragma unroll
                for (int j = 0; j < 8; j++)
                    acc[i][j] += ar[i] * br[j];
        }
    }

    #pragma unroll
    for (int i = 0; i < 8; i++) {
        int row = mBase + ((i < 4) ? (ty * 4 + i) : (64 + ty * 4 + i - 4));
        #pragma unroll
        for (int jh = 0; jh < 2; jh++) {
            int colBase = nBase + jh * 64 + tx * 4;
            float v[4];
            #pragma unroll
            for (int j = 0; j < 4; j++) {
                float val = acc[i][jh * 4 + j];
                if (EPI == 1) {
                    int col = colBase + j;
                    val += bias[col];
                    val = fmaxf(val, 0.f) + log1pf(expf(-fabsf(val)));
                    val = fminf(fmaxf(val, 1e-4f), 0.1f);
                    // transposed copy: row = b*L+t, col = d
                    int t = row & (LSEQ - 1);
                    int bb = row >> 10;
                    CT[((size_t)(bb * DM + col)) * LSEQ + t] = val;
                }
                v[j] = val;
            }
            float4 o; o.x=v[0]; o.y=v[1]; o.z=v[2]; o.w=v[3];
            *(float4*)&C[(size_t)row * ldc + colBase] = o;
        }
    }
}

// ================= 64x64 guarded SGEMM (for skinny N=80) =================
__global__ void sgemm64_k(const float* __restrict__ A, const float* __restrict__ B,
                          float* __restrict__ C,
                          int M, int N, int K, int lda, int ldb, int ldc)
{
    const int BK = 16;
    __shared__ float As[64][16];
    __shared__ float Bs[16][65];

    int tid = threadIdx.x;
    int tx = tid & 15, ty = tid >> 4;
    int rowBase = blockIdx.y * 64, colBase = blockIdx.x * 64;
    float acc[4][4] = {};

    for (int kt = 0; kt < K; kt += BK) {
        #pragma unroll
        for (int i = 0; i < 4; i++) {
            int idx = tid + i * 256;
            int m = idx >> 4, k = idx & 15;
            int gm = rowBase + m, gk = kt + k;
            As[m][k] = (gm < M && gk < K) ? A[(size_t)gm * lda + gk] : 0.f;
        }
        #pragma unroll
        for (int i = 0; i < 4; i++) {
            int idx = tid + i * 256;
            int k = idx >> 6, n = idx & 63;
            int gk = kt + k, gn = colBase + n;
            Bs[k][n] = (gk < K && gn < N) ? B[(size_t)gk * ldb + gn] : 0.f;
        }
        __syncthreads();
        #pragma unroll
        for (int kk = 0; kk < BK; kk++) {
            float a[4], b[4];
            #pragma unroll
            for (int i = 0; i < 4; i++) a[i] = As[ty * 4 + i][kk];
            #pragma unroll
            for (int j = 0; j < 4; j++) b[j] = Bs[kk][tx * 4 + j];
            #pragma unroll
            for (int i = 0; i < 4; i++)
                #pragma unroll
                for (int j = 0; j < 4; j++)
                    acc[i][j] += a[i] * b[j];
        }
        __syncthreads();
    }
    #pragma unroll
    for (int i = 0; i < 4; i++) {
        int gm = rowBase + ty * 4 + i;
        if (gm >= M) continue;
        #pragma unroll
        for (int j = 0; j < 4; j++) {
            int gn = colBase + tx * 4 + j;
            if (gn < N) C[(size_t)gm * ldc + gn] = acc[i][j];
        }
    }
}

// ============ depthwise causal conv (K=4) + SiLU + transposed copies ============
__global__ void conv_silu_k(const float* __restrict__ xr,
                            const float* __restrict__ cw,
                            const float* __restrict__ cb,
                            float* __restrict__ xs,
                            float* __restrict__ xsT,
                            float* __restrict__ gateT)
{
    int idx = blockIdx.x * blockDim.x + threadIdx.x;
    if (idx >= MROWS * DM) return;
    int d = idx % DM;
    int t = (idx / DM) % LSEQ;
    int b = idx / (DM * LSEQ);
    size_t bt = (size_t)(b * LSEQ + t);

    float acc = cb[d];
    #pragma unroll
    for (int k = 0; k < KCONV; k++) {
        int tt = t - (KCONV - 1) + k;
        if (tt >= 0)
            acc += xr[((size_t)(b * LSEQ + tt)) * W2 + d] * cw[d * KCONV + k];
    }
    float v = acc / (1.f + expf(-acc));
    xs[idx] = v;
    size_t bd = (size_t)(b * DM + d);
    xsT[bd * LSEQ + t] = v;

    float r = xr[bt * W2 + DM + d];
    gateT[bd * LSEQ + t] = r / (1.f + expf(-r));
}

// ================= fused parallel selective scan =================
// One block per (b,d). 512 threads = 32 t-chunks x 16 states.
// Phase 0: block suffix-scan of delta -> S (smem).
// Phase 1: q_t(n) = delta*u*B_n*exp(A_n*S_t), chunk-local totals.
// Phase 2: per-n warp scan of chunk totals (exclusive offsets).
// Phase 3: rebuild prefix, y = sum_n (num/(e+1e-12))*C_n + u*D, gate, store.
__global__ __launch_bounds__(512, 2) void scan_fused_k(
    const float* __restrict__ deltaT,  // [bd][t]
    const float* __restrict__ xsT,     // [bd][t]
    const float* __restrict__ gateT,   // [bd][t]
    const float* __restrict__ xp,      // [bt][80]
    const float* __restrict__ A_log,
    const float* __restrict__ Dp,
    float* __restrict__ yg)            // [bt][d]
{
    extern __shared__ float sm[];
    float* Dsm = sm;                 // 1024
    float* S   = sm + 1024;          // 1024
    float* U   = sm + 2048;          // 1024
    float* qs  = sm + 3072;          // 16384: [(t)*16 + n]
    float* tot = sm + 3072 + 16384;  // 16*33 = 528: [n*33 + c]
    float* wt  = tot + 528;          // 16

    int bd = blockIdx.x;
    int b = bd / DM, d = bd - b * DM;
    int tid = threadIdx.x;
    int lane = tid & 31, wid = tid >> 5;

    const float* dT = deltaT + (size_t)bd * LSEQ;
    const float* uT = xsT + (size_t)bd * LSEQ;
    Dsm[tid] = dT[tid];        Dsm[tid + 512] = dT[tid + 512];
    U[tid]   = uT[tid];        U[tid + 512]   = uT[tid + 512];
    __syncthreads();

    // ---- Phase 0: exclusive suffix scan (via prefix scan of reversed array)
    float a0 = Dsm[LSEQ - 1 - 2 * tid];
    float a1 = Dsm[LSEQ - 2 - 2 * tid];
    float ts = a0 + a1;
    float incl = ts;
    #pragma unroll
    for (int off = 1; off < 32; off <<= 1) {
        float v = __shfl_up_sync(0xffffffffu, incl, off);
        if (lane >= off) incl += v;
    }
    if (lane == 31) wt[wid] = incl;
    float excl = incl - ts;
    __syncthreads();
    if (wid == 0) {
        float w = (lane < 16) ? wt[lane] : 0.f;
        float wi = w;
        #pragma unroll
        for (int off = 1; off < 16; off <<= 1) {
            float v = __shfl_up_sync(0xffffffffu, wi, off);
            if (lane >= off) wi += v;
        }
        if (lane < 16) wt[lane] = wi - w;   // exclusive
    }
    __syncthreads();
    float X = excl + wt[wid];
    S[LSEQ - 1 - 2 * tid] = X;
    S[LSEQ - 2 - 2 * tid] = X + a0;
    __syncthreads();

    // ---- Phase 1
    int c = tid >> 4, n = tid & 15;
    float An = -expf(A_log[d * NST + n]);
    size_t btBase = (size_t)b * LSEQ;
    const float* Bp = xp + DRANK + n;
    float run = 0.f;
    #pragma unroll 4
    for (int j = 0; j < 32; j++) {
        int t = c * 32 + j;
        float e = expf(An * S[t]);
        float q = Dsm[t] * U[t] * Bp[(btBase + t) * XPW] * e;
        qs[(t << 4) + n] = q;
        run += q;
    }
    tot[n * 33 + c] = run;
    __syncthreads();

    // ---- Phase 2: per-n exclusive scan of 32 chunk totals (warp w <-> n=w)
    if (wid < 16) {
        float v = tot[wid * 33 + lane];
        float inc = v;
        #pragma unroll
        for (int off = 1; off < 32; off <<= 1) {
            float u2 = __shfl_up_sync(0xffffffffu, inc, off);
            if (lane >= off) inc += u2;
        }
        tot[wid * 33 + lane] = inc - v;
    }
    __syncthreads();

    // ---- Phase 3
    float num = tot[n * 33 + c];
    float Dd = Dp[d];
    const float* Cp = xp + DRANK + NST + n;
    const float* gp = gateT + (size_t)bd * LSEQ;
    float* ygp = yg + d;
    #pragma unroll 4
    for (int j = 0; j < 32; j++) {
        int t = c * 32 + j;
        num += qs[(t << 4) + n];
        float e = expf(An * S[t]);
        float yn = __fdividef(num, e + 1e-12f) * Cp[(btBase + t) * XPW];
        yn += __shfl_xor_sync(0xffffffffu, yn, 1);
        yn += __shfl_xor_sync(0xffffffffu, yn, 2);
        yn += __shfl_xor_sync(0xffffffffu, yn, 4);
        yn += __shfl_xor_sync(0xffffffffu, yn, 8);
        if (n == 0)
            ygp[(btBase + t) * DM] = (yn + U[t] * Dd) * gp[t];
    }
}

// ================= launch =================
extern "C" void kernel_launch(void* const* d_in, const int* in_sizes, int n_in,
                              void* d_out, int out_size)
{
    const float* x       = (const float*)d_in[0];
    const float* W_in    = (const float*)d_in[1];
    const float* conv_w  = (const float*)d_in[2];
    const float* conv_b  = (const float*)d_in[3];
    const float* W_x     = (const float*)d_in[4];
    const float* W_delta = (const float*)d_in[5];
    const float* b_delta = (const float*)d_in[6];
    const float* A_log   = (const float*)d_in[7];
    const float* D_param = (const float*)d_in[8];
    const float* W_out   = (const float*)d_in[9];
    float* out = (float*)d_out;

    float *p_xr, *p_xs, *p_xsT, *p_gateT, *p_xp, *p_delta, *p_deltaT, *p_yg;
    cudaGetSymbolAddress((void**)&p_xr,     g_xr);
    cudaGetSymbolAddress((void**)&p_xs,     g_xs);
    cudaGetSymbolAddress((void**)&p_xsT,    g_xsT);
    cudaGetSymbolAddress((void**)&p_gateT,  g_gateT);
    cudaGetSymbolAddress((void**)&p_xp,     g_xp);
    cudaGetSymbolAddress((void**)&p_delta,  g_delta);
    cudaGetSymbolAddress((void**)&p_deltaT, g_deltaT);
    cudaGetSymbolAddress((void**)&p_yg,     g_yg);

    const int SCAN_SMEM = (3072 + 16384 + 528 + 16) * 4;  // 80000 B
    cudaFuncSetAttribute(scan_fused_k,
                         cudaFuncAttributeMaxDynamicSharedMemorySize, SCAN_SMEM);

    // 1) xr = x @ W_in   (2048 x 1536, K=768)
    sgemm128_k<0><<<dim3(W2 / 128, MROWS / 128), 256>>>(
        x, W_in, nullptr, p_xr, nullptr, MROWS, W2, DM, DM, W2, W2);

    // 2) conv + silu (+ transposed xs, silu(res))
    conv_silu_k<<<(MROWS * DM + 255) / 256, 256>>>(p_xr, conv_w, conv_b,
                                                   p_xs, p_xsT, p_gateT);

    // 3) xp = xs @ W_x   (2048 x 80, K=768)
    sgemm64_k<<<dim3((XPW + 63) / 64, MROWS / 64), 256>>>(
        p_xs, W_x, p_xp, MROWS, XPW, DM, DM, XPW, XPW);

    // 4) delta = clip(softplus(xp[:,:48] @ W_delta + b)), plus transposed copy
    sgemm128_k<1><<<dim3(DM / 128, MROWS / 128), 256>>>(
        p_xp, W_delta, b_delta, p_delta, p_deltaT, MROWS, DM, DRANK, XPW, DM, DM);

    // 5) fused parallel selective scan + gate
    scan_fused_k<<<B_SZ * DM, 512, SCAN_SMEM>>>(p_deltaT, p_xsT, p_gateT, p_xp,
                                                A_log, D_param, p_yg);

    // 6) out = yg @ W_out   (2048 x 768, K=768)
    sgemm128_k<0><<<dim3(DM / 128, MROWS / 128), 256>>>(
        p_yg, W_out, nullptr, out, nullptr, MROWS, DM, DM, DM, DM, DM);
}

// round 4
// speedup vs baseline: 5.5644x; 1.4199x over previous
#include <cuda_runtime.h>
#include <cuda_bf16.h>
#include <math.h>
#include <stdint.h>

#define B_SZ   2
#define LSEQ   1024
#define DM     768
#define NST    16
#define KCONV  4
#define DRANK  48
#define XPW    (DRANK + 2*NST)   // 80
#define W2     (2*DM)            // 1536
#define MROWS  (B_SZ*LSEQ)       // 2048

// ---------------- device scratch ----------------
__device__ float g_xr[(size_t)MROWS * W2];
__device__ float g_xs[(size_t)MROWS * DM];
__device__ float g_xsT[(size_t)B_SZ * DM * LSEQ];
__device__ float g_gateT[(size_t)B_SZ * DM * LSEQ];
__device__ float g_xp[(size_t)MROWS * XPW];
__device__ float g_delta[(size_t)MROWS * DM];
__device__ float g_deltaT[(size_t)B_SZ * DM * LSEQ];
__device__ float g_yg[(size_t)MROWS * DM];
__device__ __nv_bfloat16 g_Ah[(size_t)MROWS * DM];
__device__ __nv_bfloat16 g_Al[(size_t)MROWS * DM];
__device__ __nv_bfloat16 g_WinTh[(size_t)W2 * DM];
__device__ __nv_bfloat16 g_WinTl[(size_t)W2 * DM];
__device__ __nv_bfloat16 g_WoutTh[(size_t)DM * DM];
__device__ __nv_bfloat16 g_WoutTl[(size_t)DM * DM];

// ================= HMMA (mma.sync) bf16-split GEMM =================
// C(MxN) = A(MxK) * W^T(NxK), A split hi/lo, W split hi/lo, 3 passes.
// CTA 128x128, 8 warps (2M x 4N), warp tile 64x32, K-chunk 32, cp.async 2-stage.
#define KC     32
#define SROW   40                 // smem row stride in bf16 (80 B) - conflict-free ldmatrix
#define SROWB  80
#define TILEB  (128 * SROWB)      // 10240 B per tensor tile
#define STAGEB (4 * TILEB)        // Ah, Al, Bh, Bl

__device__ __forceinline__ uint32_t smem_u32(const void* p) {
    uint32_t a;
    asm("{ .reg .u64 t; cvta.to.shared.u64 t, %1; cvt.u32.u64 %0, t; }" : "=r"(a) : "l"(p));
    return a;
}

__device__ __forceinline__ void ldsm4(uint32_t* r, uint32_t addr) {
    asm volatile("ldmatrix.sync.aligned.m8n8.x4.shared.b16 {%0,%1,%2,%3}, [%4];"
                 : "=r"(r[0]), "=r"(r[1]), "=r"(r[2]), "=r"(r[3]) : "r"(addr));
}

__device__ __forceinline__ void mma16816(float* d, const uint32_t* a, const uint32_t* b) {
    asm volatile(
        "mma.sync.aligned.m16n8k16.row.col.f32.bf16.bf16.f32 "
        "{%0,%1,%2,%3},{%4,%5,%6,%7},{%8,%9},{%0,%1,%2,%3};"
        : "+f"(d[0]), "+f"(d[1]), "+f"(d[2]), "+f"(d[3])
        : "r"(a[0]), "r"(a[1]), "r"(a[2]), "r"(a[3]), "r"(b[0]), "r"(b[1]));
}

__device__ __forceinline__ void cp16(uint32_t saddr, const void* gaddr) {
    asm volatile("cp.async.cg.shared.global [%0], [%1], 16;" :: "r"(saddr), "l"(gaddr));
}

// load A fragments for one 64x32 warp tile: af[kstep][matom][4]
__device__ __forceinline__ void load_afrag(uint32_t af[2][4][4], uint32_t base, int lane) {
    int r = lane & 15;
    int kb = (lane >> 4) * 8;
    #pragma unroll
    for (int ks = 0; ks < 2; ks++)
        #pragma unroll
        for (int ma = 0; ma < 4; ma++)
            ldsm4(af[ks][ma], base + (uint32_t)((ma * 16 + r) * SROWB + (ks * 16 + kb) * 2));
}
// load B fragments: bf[kstep][npair][4]; npair p covers n-atoms 2p (regs0-1), 2p+1 (regs2-3)
__device__ __forceinline__ void load_bfrag(uint32_t bf[2][2][4], uint32_t base, int lane) {
    int nr = (lane & 7) + ((lane >> 4) * 8);
    int kb = ((lane >> 3) & 1) * 8;
    #pragma unroll
    for (int ks = 0; ks < 2; ks++)
        #pragma unroll
        for (int np = 0; np < 2; np++)
            ldsm4(bf[ks][np], base + (uint32_t)((np * 16 + nr) * SROWB + (ks * 16 + kb) * 2));
}

__device__ __forceinline__ void mma_all(float d[4][4][4],
                                        uint32_t af[2][4][4], uint32_t bf[2][2][4]) {
    #pragma unroll
    for (int ks = 0; ks < 2; ks++)
        #pragma unroll
        for (int ma = 0; ma < 4; ma++)
            #pragma unroll
            for (int na = 0; na < 4; na++)
                mma16816(d[ma][na], af[ks][ma], &bf[ks][na >> 1][(na & 1) * 2]);
}

__global__ __launch_bounds__(256, 2) void hmma_gemm_k(
    const __nv_bfloat16* __restrict__ Ah, const __nv_bfloat16* __restrict__ Al,
    const __nv_bfloat16* __restrict__ Bh, const __nv_bfloat16* __restrict__ Bl,
    float* __restrict__ C, int M, int N, int K)
{
    extern __shared__ char smem[];
    uint32_t sb = smem_u32(smem);
    int tid = threadIdx.x;
    int wid = tid >> 5, lane = tid & 31;
    int mBase = blockIdx.y * 128, nBase = blockIdx.x * 128;
    int warpM = (wid & 1) * 64, warpN = (wid >> 1) * 32;

    const __nv_bfloat16* srcs[4] = { Ah, Al, Bh, Bl };
    int rowBases[4] = { mBase, mBase, nBase, nBase };

    float d[4][4][4] = {};
    const int nch = K / KC;

    // ---- async load of one stage
    auto issue = [&](int s, int k0) {
        uint32_t stb = sb + (uint32_t)s * STAGEB;
        #pragma unroll
        for (int ten = 0; ten < 4; ten++) {
            const __nv_bfloat16* src = srcs[ten];
            int rb = rowBases[ten];
            #pragma unroll
            for (int i = 0; i < 2; i++) {
                int idx = tid + (i << 8);       // 0..511
                int r = idx >> 2, c = idx & 3;  // 128 rows x 4 16B-chunks
                cp16(stb + (uint32_t)(ten * TILEB + r * SROWB + c * 16),
                     src + (size_t)(rb + r) * K + k0 + c * 8);
            }
        }
        asm volatile("cp.async.commit_group;" ::: "memory");
    };

    issue(0, 0);

    uint32_t af[2][4][4], bfm[2][2][4];

    for (int c = 0; c < nch; c++) {
        asm volatile("cp.async.wait_group 0;" ::: "memory");
        __syncthreads();
        if (c + 1 < nch) issue((c + 1) & 1, (c + 1) * KC);

        uint32_t stb = sb + (uint32_t)(c & 1) * STAGEB;
        uint32_t aBaseH = stb + warpM * SROWB;
        uint32_t aBaseL = stb + TILEB + warpM * SROWB;
        uint32_t bBaseH = stb + 2 * TILEB + warpN * SROWB;
        uint32_t bBaseL = stb + 3 * TILEB + warpN * SROWB;

        load_afrag(af, aBaseH, lane);
        load_bfrag(bfm, bBaseH, lane);
        mma_all(d, af, bfm);              // hh
        load_afrag(af, aBaseL, lane);
        mma_all(d, af, bfm);              // lh
        load_bfrag(bfm, bBaseL, lane);
        load_afrag(af, aBaseH, lane);
        mma_all(d, af, bfm);              // hl
        __syncthreads();
    }

    // epilogue
    int g = lane >> 2, t = lane & 3;
    #pragma unroll
    for (int ma = 0; ma < 4; ma++) {
        int row0 = mBase + warpM + ma * 16 + g;
        #pragma unroll
        for (int na = 0; na < 4; na++) {
            int col = nBase + warpN + na * 8 + t * 2;
            float2 lo = make_float2(d[ma][na][0], d[ma][na][1]);
            float2 hi = make_float2(d[ma][na][2], d[ma][na][3]);
            *(float2*)&C[(size_t)row0 * N + col] = lo;
            *(float2*)&C[(size_t)(row0 + 8) * N + col] = hi;
        }
    }
}

// ================= fp32 -> bf16 hi/lo split =================
__global__ void cvt_split_k(const float* __restrict__ src,
                            __nv_bfloat16* __restrict__ hi,
                            __nv_bfloat16* __restrict__ lo, int n4)
{
    int i = blockIdx.x * blockDim.x + threadIdx.x;
    if (i >= n4) return;
    float4 f = ((const float4*)src)[i];
    __nv_bfloat16 h0 = __float2bfloat16(f.x), h1 = __float2bfloat16(f.y);
    __nv_bfloat16 h2 = __float2bfloat16(f.z), h3 = __float2bfloat16(f.w);
    __nv_bfloat16 l0 = __float2bfloat16(f.x - __bfloat162float(h0));
    __nv_bfloat16 l1 = __float2bfloat16(f.y - __bfloat162float(h1));
    __nv_bfloat16 l2 = __float2bfloat16(f.z - __bfloat162float(h2));
    __nv_bfloat16 l3 = __float2bfloat16(f.w - __bfloat162float(h3));
    ((__nv_bfloat162*)hi)[2 * i]     = __nv_bfloat162(h0, h1);
    ((__nv_bfloat162*)hi)[2 * i + 1] = __nv_bfloat162(h2, h3);
    ((__nv_bfloat162*)lo)[2 * i]     = __nv_bfloat162(l0, l1);
    ((__nv_bfloat162*)lo)[2 * i + 1] = __nv_bfloat162(l2, l3);
}

// ============ W [K,N] fp32 -> W^T [N,K] bf16 hi/lo ============
__global__ void wtrans_k(const float* __restrict__ W,
                         __nv_bfloat16* __restrict__ hiT,
                         __nv_bfloat16* __restrict__ loT, int K, int N)
{
    __shared__ float t[32][33];
    int n0 = blockIdx.x * 32, k0 = blockIdx.y * 32;
    for (int i = threadIdx.y; i < 32; i += 8)
        t[i][threadIdx.x] = W[(size_t)(k0 + i) * N + n0 + threadIdx.x];
    __syncthreads();
    for (int i = threadIdx.y; i < 32; i += 8) {
        float f = t[threadIdx.x][i];
        __nv_bfloat16 h = __float2bfloat16(f);
        __nv_bfloat16 l = __float2bfloat16(f - __bfloat162float(h));
        size_t o = (size_t)(n0 + i) * K + k0 + threadIdx.x;
        hiT[o] = h;
        loT[o] = l;
    }
}

// ================= 64x64 guarded SGEMM (skinny N=80) =================
__global__ void sgemm64_k(const float* __restrict__ A, const float* __restrict__ B,
                          float* __restrict__ C,
                          int M, int N, int K, int lda, int ldb, int ldc)
{
    const int BK = 16;
    __shared__ float As[64][16];
    __shared__ float Bs[16][65];
    int tid = threadIdx.x;
    int tx = tid & 15, ty = tid >> 4;
    int rowBase = blockIdx.y * 64, colBase = blockIdx.x * 64;
    float acc[4][4] = {};
    for (int kt = 0; kt < K; kt += BK) {
        #pragma unroll
        for (int i = 0; i < 4; i++) {
            int idx = tid + i * 256;
            int m = idx >> 4, k = idx & 15;
            int gm = rowBase + m, gk = kt + k;
            As[m][k] = (gm < M && gk < K) ? A[(size_t)gm * lda + gk] : 0.f;
        }
        #pragma unroll
        for (int i = 0; i < 4; i++) {
            int idx = tid + i * 256;
            int k = idx >> 6, n = idx & 63;
            int gk = kt + k, gn = colBase + n;
            Bs[k][n] = (gk < K && gn < N) ? B[(size_t)gk * ldb + gn] : 0.f;
        }
        __syncthreads();
        #pragma unroll
        for (int kk = 0; kk < BK; kk++) {
            float a[4], b[4];
            #pragma unroll
            for (int i = 0; i < 4; i++) a[i] = As[ty * 4 + i][kk];
            #pragma unroll
            for (int j = 0; j < 4; j++) b[j] = Bs[kk][tx * 4 + j];
            #pragma unroll
            for (int i = 0; i < 4; i++)
                #pragma unroll
                for (int j = 0; j < 4; j++)
                    acc[i][j] += a[i] * b[j];
        }
        __syncthreads();
    }
    #pragma unroll
    for (int i = 0; i < 4; i++) {
        int gm = rowBase + ty * 4 + i;
        if (gm >= M) continue;
        #pragma unroll
        for (int j = 0; j < 4; j++) {
            int gn = colBase + tx * 4 + j;
            if (gn < N) C[(size_t)gm * ldc + gn] = acc[i][j];
        }
    }
}

// ================= delta GEMM (128 tile) + softplus epilogue =================
__global__ __launch_bounds__(256) void sgemm128_sp_k(
    const float* __restrict__ A, const float* __restrict__ B,
    const float* __restrict__ bias, float* __restrict__ C,
    float* __restrict__ CT,
    int M, int N, int K, int lda, int ldb, int ldc)
{
    __shared__ float As[8][128];
    __shared__ float Bs[8][128];
    int tid = threadIdx.x;
    int tx = tid & 15, ty = tid >> 4;
    int mBase = blockIdx.y * 128, nBase = blockIdx.x * 128;
    int arow = tid >> 1, acol = (tid & 1) * 4;
    int brow = tid >> 5, bcol = (tid & 31) * 4;
    float acc[8][8] = {};
    for (int k0 = 0; k0 < K; k0 += 8) {
        float4 av = *(const float4*)&A[(size_t)(mBase + arow) * lda + k0 + acol];
        float4 bv = *(const float4*)&B[(size_t)(k0 + brow) * ldb + nBase + bcol];
        __syncthreads();
        As[acol + 0][arow] = av.x; As[acol + 1][arow] = av.y;
        As[acol + 2][arow] = av.z; As[acol + 3][arow] = av.w;
        *(float4*)&Bs[brow][bcol] = bv;
        __syncthreads();
        #pragma unroll
        for (int kk = 0; kk < 8; kk++) {
            float ar[8], br[8];
            float4 a0 = *(const float4*)&As[kk][ty * 4];
            float4 a1 = *(const float4*)&As[kk][64 + ty * 4];
            float4 b0 = *(const float4*)&Bs[kk][tx * 4];
            float4 b1 = *(const float4*)&Bs[kk][64 + tx * 4];
            ar[0]=a0.x; ar[1]=a0.y; ar[2]=a0.z; ar[3]=a0.w;
            ar[4]=a1.x; ar[5]=a1.y; ar[6]=a1.z; ar[7]=a1.w;
            br[0]=b0.x; br[1]=b0.y; br[2]=b0.z; br[3]=b0.w;
            br[4]=b1.x; br[5]=b1.y; br[6]=b1.z; br[7]=b1.w;
            #pragma unroll
            for (int i = 0; i < 8; i++)
                #pragma unroll
                for (int j = 0; j < 8; j++)
                    acc[i][j] += ar[i] * br[j];
        }
    }
    #pragma unroll
    for (int i = 0; i < 8; i++) {
        int row = mBase + ((i < 4) ? (ty * 4 + i) : (64 + ty * 4 + i - 4));
        #pragma unroll
        for (int jh = 0; jh < 2; jh++) {
            int colBase = nBase + jh * 64 + tx * 4;
            float v[4];
            #pragma unroll
            for (int j = 0; j < 4; j++) {
                int col = colBase + j;
                float val = acc[i][jh * 4 + j] + bias[col];
                val = fmaxf(val, 0.f) + log1pf(expf(-fabsf(val)));
                val = fminf(fmaxf(val, 1e-4f), 0.1f);
                int t = row & (LSEQ - 1);
                int bb = row >> 10;
                CT[((size_t)(bb * DM + col)) * LSEQ + t] = val;
                v[j] = val;
            }
            float4 o; o.x=v[0]; o.y=v[1]; o.z=v[2]; o.w=v[3];
            *(float4*)&C[(size_t)row * ldc + colBase] = o;
        }
    }
}

// ============ depthwise causal conv + SiLU + transposed copies ============
__global__ void conv_silu_k(const float* __restrict__ xr,
                            const float* __restrict__ cw,
                            const float* __restrict__ cb,
                            float* __restrict__ xs,
                            float* __restrict__ xsT,
                            float* __restrict__ gateT)
{
    int idx = blockIdx.x * blockDim.x + threadIdx.x;
    if (idx >= MROWS * DM) return;
    int d = idx % DM;
    int t = (idx / DM) % LSEQ;
    int b = idx / (DM * LSEQ);
    size_t bt = (size_t)(b * LSEQ + t);
    float acc = cb[d];
    #pragma unroll
    for (int k = 0; k < KCONV; k++) {
        int tt = t - (KCONV - 1) + k;
        if (tt >= 0)
            acc += xr[((size_t)(b * LSEQ + tt)) * W2 + d] * cw[d * KCONV + k];
    }
    float v = acc / (1.f + expf(-acc));
    xs[idx] = v;
    size_t bd = (size_t)(b * DM + d);
    xsT[bd * LSEQ + t] = v;
    float r = xr[bt * W2 + DM + d];
    gateT[bd * LSEQ + t] = r / (1.f + expf(-r));
}

// ================= fused parallel selective scan =================
__global__ __launch_bounds__(512, 2) void scan_fused_k(
    const float* __restrict__ deltaT, const float* __restrict__ xsT,
    const float* __restrict__ gateT, const float* __restrict__ xp,
    const float* __restrict__ A_log, const float* __restrict__ Dp,
    float* __restrict__ yg)
{
    extern __shared__ float sm[];
    float* Dsm = sm;
    float* S   = sm + 1024;
    float* U   = sm + 2048;
    float* qs  = sm + 3072;
    float* tot = sm + 3072 + 16384;
    float* wt  = tot + 528;

    int bd = blockIdx.x;
    int b = bd / DM, d = bd - b * DM;
    int tid = threadIdx.x;
    int lane = tid & 31, wid = tid >> 5;

    const float* dT = deltaT + (size_t)bd * LSEQ;
    const float* uT = xsT + (size_t)bd * LSEQ;
    Dsm[tid] = dT[tid];        Dsm[tid + 512] = dT[tid + 512];
    U[tid]   = uT[tid];        U[tid + 512]   = uT[tid + 512];
    __syncthreads();

    float a0 = Dsm[LSEQ - 1 - 2 * tid];
    float a1 = Dsm[LSEQ - 2 - 2 * tid];
    float ts = a0 + a1;
    float incl = ts;
    #pragma unroll
    for (int off = 1; off < 32; off <<= 1) {
        float v = __shfl_up_sync(0xffffffffu, incl, off);
        if (lane >= off) incl += v;
    }
    if (lane == 31) wt[wid] = incl;
    float excl = incl - ts;
    __syncthreads();
    if (wid == 0) {
        float w = (lane < 16) ? wt[lane] : 0.f;
        float wi = w;
        #pragma unroll
        for (int off = 1; off < 16; off <<= 1) {
            float v = __shfl_up_sync(0xffffffffu, wi, off);
            if (lane >= off) wi += v;
        }
        if (lane < 16) wt[lane] = wi - w;
    }
    __syncthreads();
    float X = excl + wt[wid];
    S[LSEQ - 1 - 2 * tid] = X;
    S[LSEQ - 2 - 2 * tid] = X + a0;
    __syncthreads();

    int c = tid >> 4, n = tid & 15;
    float An = -expf(A_log[d * NST + n]);
    size_t btBase = (size_t)b * LSEQ;
    const float* Bp = xp + DRANK + n;
    float run = 0.f;
    #pragma unroll 4
    for (int j = 0; j < 32; j++) {
        int t = c * 32 + j;
        float e = expf(An * S[t]);
        float q = Dsm[t] * U[t] * Bp[(btBase + t) * XPW] * e;
        qs[(t << 4) + n] = q;
        run += q;
    }
    tot[n * 33 + c] = run;
    __syncthreads();

    if (wid < 16) {
        float v = tot[wid * 33 + lane];
        float inc = v;
        #pragma unroll
        for (int off = 1; off < 32; off <<= 1) {
            float u2 = __shfl_up_sync(0xffffffffu, inc, off);
            if (lane >= off) inc += u2;
        }
        tot[wid * 33 + lane] = inc - v;
    }
    __syncthreads();

    float num = tot[n * 33 + c];
    float Dd = Dp[d];
    const float* Cp = xp + DRANK + NST + n;
    const float* gp = gateT + (size_t)bd * LSEQ;
    float* ygp = yg + d;
    #pragma unroll 4
    for (int j = 0; j < 32; j++) {
        int t = c * 32 + j;
        num += qs[(t << 4) + n];
        float e = expf(An * S[t]);
        float yn = __fdividef(num, e + 1e-12f) * Cp[(btBase + t) * XPW];
        yn += __shfl_xor_sync(0xffffffffu, yn, 1);
        yn += __shfl_xor_sync(0xffffffffu, yn, 2);
        yn += __shfl_xor_sync(0xffffffffu, yn, 4);
        yn += __shfl_xor_sync(0xffffffffu, yn, 8);
        if (n == 0)
            ygp[(btBase + t) * DM] = (yn + U[t] * Dd) * gp[t];
    }
}

// ================= launch =================
extern "C" void kernel_launch(void* const* d_in, const int* in_sizes, int n_in,
                              void* d_out, int out_size)
{
    const float* x       = (const float*)d_in[0];
    const float* W_in    = (const float*)d_in[1];
    const float* conv_w  = (const float*)d_in[2];
    const float* conv_b  = (const float*)d_in[3];
    const float* W_x     = (const float*)d_in[4];
    const float* W_delta = (const float*)d_in[5];
    const float* b_delta = (const float*)d_in[6];
    const float* A_log   = (const float*)d_in[7];
    const float* D_param = (const float*)d_in[8];
    const float* W_out   = (const float*)d_in[9];
    float* out = (float*)d_out;

    float *p_xr, *p_xs, *p_xsT, *p_gateT, *p_xp, *p_delta, *p_deltaT, *p_yg;
    __nv_bfloat16 *p_Ah, *p_Al, *p_WinTh, *p_WinTl, *p_WoutTh, *p_WoutTl;
    cudaGetSymbolAddress((void**)&p_xr,     g_xr);
    cudaGetSymbolAddress((void**)&p_xs,     g_xs);
    cudaGetSymbolAddress((void**)&p_xsT,    g_xsT);
    cudaGetSymbolAddress((void**)&p_gateT,  g_gateT);
    cudaGetSymbolAddress((void**)&p_xp,     g_xp);
    cudaGetSymbolAddress((void**)&p_delta,  g_delta);
    cudaGetSymbolAddress((void**)&p_deltaT, g_deltaT);
    cudaGetSymbolAddress((void**)&p_yg,     g_yg);
    cudaGetSymbolAddress((void**)&p_Ah,     g_Ah);
    cudaGetSymbolAddress((void**)&p_Al,     g_Al);
    cudaGetSymbolAddress((void**)&p_WinTh,  g_WinTh);
    cudaGetSymbolAddress((void**)&p_WinTl,  g_WinTl);
    cudaGetSymbolAddress((void**)&p_WoutTh, g_WoutTh);
    cudaGetSymbolAddress((void**)&p_WoutTl, g_WoutTl);

    const int SCAN_SMEM = (3072 + 16384 + 528 + 16) * 4;
    cudaFuncSetAttribute(scan_fused_k,
                         cudaFuncAttributeMaxDynamicSharedMemorySize, SCAN_SMEM);
    const int HM_SMEM = 2 * STAGEB;   // 81920
    cudaFuncSetAttribute(hmma_gemm_k,
                         cudaFuncAttributeMaxDynamicSharedMemorySize, HM_SMEM);

    // 0) operand conversions
    cvt_split_k<<<(MROWS * DM / 4 + 255) / 256, 256>>>(x, p_Ah, p_Al, MROWS * DM / 4);
    wtrans_k<<<dim3(W2 / 32, DM / 32), dim3(32, 8)>>>(W_in, p_WinTh, p_WinTl, DM, W2);
    wtrans_k<<<dim3(DM / 32, DM / 32), dim3(32, 8)>>>(W_out, p_WoutTh, p_WoutTl, DM, DM);

    // 1) xr = x @ W_in (HMMA, 2048x1536, K=768)
    hmma_gemm_k<<<dim3(W2 / 128, MROWS / 128), 256, HM_SMEM>>>(
        p_Ah, p_Al, p_WinTh, p_WinTl, p_xr, MROWS, W2, DM);

    // 2) conv + silu
    conv_silu_k<<<(MROWS * DM + 255) / 256, 256>>>(p_xr, conv_w, conv_b,
                                                   p_xs, p_xsT, p_gateT);

    // 3) xp = xs @ W_x
    sgemm64_k<<<dim3((XPW + 63) / 64, MROWS / 64), 256>>>(
        p_xs, W_x, p_xp, MROWS, XPW, DM, DM, XPW, XPW);

    // 4) delta
    sgemm128_sp_k<<<dim3(DM / 128, MROWS / 128), 256>>>(
        p_xp, W_delta, b_delta, p_delta, p_deltaT, MROWS, DM, DRANK, XPW, DM, DM);

    // 5) fused scan
    scan_fused_k<<<B_SZ * DM, 512, SCAN_SMEM>>>(p_deltaT, p_xsT, p_gateT, p_xp,
                                                A_log, D_param, p_yg);

    // 6) out = yg @ W_out (HMMA, 2048x768, K=768)
    cvt_split_k<<<(MROWS * DM / 4 + 255) / 256, 256>>>(p_yg, p_Ah, p_Al, MROWS * DM / 4);
    hmma_gemm_k<<<dim3(DM / 128, MROWS / 128), 256, HM_SMEM>>>(
        p_Ah, p_Al, p_WoutTh, p_WoutTl, out, MROWS, DM, DM);
}